// round 16
// baseline (speedup 1.0000x reference)
#include <cuda_runtime.h>

#define NB 64
#define LC 4096
#define HD 768
#define PD 128
#define BUDGETF 200.0f

// Scratch (allocation-free rule: __device__ globals)
__device__ float d_U[NB * HD];      // u_b = Wc @ q_b
__device__ float d_qbias[NB];       // q_b . bc
__device__ int   d_len[NB];         // valid context length per batch
__device__ float d_s[NB * LC];      // match scores (only [0,len) valid)
__device__ int   d_done;            // score-completion counter (grid barrier)

// ---------------------------------------------------------------------------
// Kernel 1 (fused, grid 64x4): every block recomputes q_b (redundant stage A,
// Wq L2-resident), then its 192-row chunk of u_b. Chunk-0 blocks also do the
// mask count and qbias. Resets d_done (stream-ordered before score_tau).
// ---------------------------------------------------------------------------
__global__ void __launch_bounds__(512) proj_kernel(const float* __restrict__ qr,
                                                   const float* __restrict__ Wq,
                                                   const float* __restrict__ bq,
                                                   const float* __restrict__ Wc,
                                                   const float* __restrict__ bc,
                                                   const int* __restrict__ mask) {
    int b = blockIdx.x;
    int chunk = blockIdx.y;           // 0..3
    __shared__ float sh_qr[HD];
    __shared__ float sh_part[512];
    __shared__ float sh_q[PD];
    __shared__ int sh_cnt[16];
    int tid = threadIdx.x;
    int warp = tid >> 5, lane = tid & 31;

    if (b == 0 && chunk == 0 && tid == 0) d_done = 0;   // reset grid barrier

    for (int i = tid; i < HD; i += 512) sh_qr[i] = qr[b * HD + i];

    if (chunk == 0) {
        int cnt = 0;
        for (int i = tid; i < LC; i += 512) cnt += mask[b * LC + i];
        #pragma unroll
        for (int off = 16; off; off >>= 1)
            cnt += __shfl_xor_sync(0xffffffffu, cnt, off);
        if (lane == 0) sh_cnt[warp] = cnt;
    }
    __syncthreads();
    if (chunk == 0 && tid == 0) {
        int t = 0;
        #pragma unroll
        for (int w = 0; w < 16; w++) t += sh_cnt[w];
        d_len[b] = t;
    }

    // Stage A (redundant per block): q[p] = qr . Wq[:,p] + bq[p]
    int p = tid & 127;
    int slice = tid >> 7;             // 0..3
    int h0 = slice * (HD / 4);
    float a0 = 0.f, a1 = 0.f, a2 = 0.f, a3 = 0.f;
    #pragma unroll 4
    for (int h = h0; h < h0 + HD / 4; h += 4) {
        a0 = fmaf(sh_qr[h + 0], Wq[(h + 0) * PD + p], a0);
        a1 = fmaf(sh_qr[h + 1], Wq[(h + 1) * PD + p], a1);
        a2 = fmaf(sh_qr[h + 2], Wq[(h + 2) * PD + p], a2);
        a3 = fmaf(sh_qr[h + 3], Wq[(h + 3) * PD + p], a3);
    }
    sh_part[tid] = (a0 + a1) + (a2 + a3);
    __syncthreads();

    if (tid < PD) {
        sh_q[tid] = sh_part[tid] + sh_part[PD + tid] + sh_part[2 * PD + tid]
                  + sh_part[3 * PD + tid] + bq[tid];
    }
    __syncthreads();

    if (chunk == 0 && tid < 32) {
        float v = 0.f;
        #pragma unroll
        for (int k = 0; k < 4; k++)
            v = fmaf(sh_q[tid + 32 * k], bc[tid + 32 * k], v);
        #pragma unroll
        for (int off = 16; off; off >>= 1)
            v += __shfl_xor_sync(0xffffffffu, v, off);
        if (tid == 0) d_qbias[b] = v;
    }

    // Stage B: u[h] = Wc[h,:] . q for this chunk's 192 rows (16 warps)
    for (int hh = warp; hh < HD / 4; hh += 16) {
        int h = chunk * (HD / 4) + hh;
        const float* wr = Wc + (size_t)h * PD;
        float acc = wr[lane] * sh_q[lane];
        acc = fmaf(wr[lane + 32], sh_q[lane + 32], acc);
        acc = fmaf(wr[lane + 64], sh_q[lane + 64], acc);
        acc = fmaf(wr[lane + 96], sh_q[lane + 96], acc);
        #pragma unroll
        for (int off = 16; off; off >>= 1)
            acc += __shfl_xor_sync(0xffffffffu, acc, off);
        if (lane == 0) d_U[b * HD + h] = acc;
    }
}

// ---------------------------------------------------------------------------
// Kernel 2 (fused score + tau):
//  Phase 1 (all 592 blocks, 512 thr = 9472 warps, same row-interleaved loop
//           as the measured-ceiling 1184x256 form).
//  Grid barrier: threadfence + atomicAdd; blocks 0..63 spin (>=232 workers
//           always co-resident with the 64 spinners -> progress guaranteed).
//  Phase 2 (blocks 0..63): unchanged 512-thread tau solve + scatter.
// ---------------------------------------------------------------------------
#define ST_BLOCKS 592
#define ST_WARPS (ST_BLOCKS * 16)

__device__ __forceinline__ float clip01(float v) {
    return fminf(fmaxf(v, 0.f), 1.f);
}

__global__ void __launch_bounds__(512) score_tau_kernel(
        const float* __restrict__ ctx,
        const int* __restrict__ qe_arr,
        float* __restrict__ out) {
    __shared__ int sh_len[NB];
    __shared__ float sh_qb[NB];
    __shared__ float redf[2][16 * 7];
    __shared__ float sh_tot[2][8];
    int tid = threadIdx.x;
    int warp = tid >> 5, lane = tid & 31;

    if (tid < NB) { sh_len[tid] = d_len[tid]; sh_qb[tid] = d_qbias[tid]; }
    __syncthreads();

    // ---- Phase 1: score ----
    int gw = blockIdx.x * 16 + warp;
    for (int r = gw; r < NB * LC; r += ST_WARPS) {
        int b = r >> 12;                 // LC = 4096
        int j = r & (LC - 1);
        if (j >= sh_len[b]) continue;    // uniform within warp

        const float4* row = (const float4*)(ctx + (size_t)r * HD);
        const float4* u4  = (const float4*)(d_U + b * HD);
        float acc = 0.f;
        #pragma unroll
        for (int i = 0; i < 6; i++) {    // 192 float4 / 32 lanes
            float4 v = __ldcs(row + lane + 32 * i);
            float4 w = __ldg(u4 + lane + 32 * i);
            acc = fmaf(v.x, w.x, acc);
            acc = fmaf(v.y, w.y, acc);
            acc = fmaf(v.z, w.z, acc);
            acc = fmaf(v.w, w.w, acc);
        }
        #pragma unroll
        for (int off = 16; off; off >>= 1)
            acc += __shfl_xor_sync(0xffffffffu, acc, off);
        if (lane == 0) d_s[r] = acc + sh_qb[b];
    }

    // ---- Grid barrier ----
    __syncthreads();
    __threadfence();                     // publish d_s before signalling
    if (tid == 0) atomicAdd(&d_done, 1);
    if (blockIdx.x >= NB) return;        // workers done

    if (tid == 0) {
        while (atomicAdd(&d_done, 0) < ST_BLOCKS) { }
    }
    __syncthreads();
    __threadfence();                     // acquire: d_s reads see all writes

    // ---- Phase 2: tau solve + scatter for batch b = blockIdx.x ----
    int b = blockIdx.x;
    const int NT = 512;
    int len = sh_len[b];
    const float* sp = d_s + b * LC;

    float v[8];
    #pragma unroll
    for (int k = 0; k < 8; k++) {
        int i = tid + k * NT;
        v[k] = (i < len) ? sp[i] : -100000.0f;
    }

    float mx = -100000.0f, sum0 = 0.f;
    #pragma unroll
    for (int k = 0; k < 8; k++) {
        mx = fmaxf(mx, v[k]);
        sum0 += clip01(v[k]);
    }
    {
        #pragma unroll
        for (int off = 16; off; off >>= 1) {
            mx   = fmaxf(mx, __shfl_xor_sync(0xffffffffu, mx, off));
            sum0 += __shfl_xor_sync(0xffffffffu, sum0, off);
        }
        if (lane == 0) { redf[0][warp * 2] = mx; redf[0][warp * 2 + 1] = sum0; }
        __syncthreads();
        if (tid == 0) {
            float a = redf[0][0], s = redf[0][1];
            #pragma unroll
            for (int w = 1; w < 16; w++) {
                a = fmaxf(a, redf[0][w * 2]);
                s += redf[0][w * 2 + 1];
            }
            sh_tot[1][0] = a; sh_tot[1][1] = s;
        }
        __syncthreads();
        mx = sh_tot[1][0]; sum0 = sh_tot[1][1];
    }

    float tau = 0.f;
    if (sum0 > BUDGETF) {
        float lo = 0.f, hi = mx;
        float slo = sum0, shi = 0.f;
        for (int it = 0; it < 6; it++) {
            int par = it & 1;
            float step = (hi - lo) * 0.125f;
            float part[7];
            #pragma unroll
            for (int c = 0; c < 7; c++) part[c] = 0.f;
            #pragma unroll
            for (int k = 0; k < 8; k++) {
                float x = v[k] - lo;
                #pragma unroll
                for (int c = 0; c < 7; c++)
                    part[c] += clip01(x - (c + 1) * step);
            }
            #pragma unroll
            for (int c = 0; c < 7; c++) {
                #pragma unroll
                for (int off = 16; off; off >>= 1)
                    part[c] += __shfl_xor_sync(0xffffffffu, part[c], off);
            }
            if (lane == 0) {
                #pragma unroll
                for (int c = 0; c < 7; c++) redf[par][warp * 7 + c] = part[c];
            }
            __syncthreads();               // barrier 1: partials ready
            if (tid < 7) {
                float t = redf[par][tid];
                #pragma unroll
                for (int w = 1; w < 16; w++) t += redf[par][w * 7 + tid];
                sh_tot[par][tid] = t;
            }
            __syncthreads();               // barrier 2: totals ready
            float nlo = lo, nhi = hi, nslo = slo, nshi = shi;
            bool crossed = false;
            #pragma unroll
            for (int c = 0; c < 7; c++) {
                float tc = lo + (c + 1) * step;
                float Sc = sh_tot[par][c];
                if (!crossed) {
                    if (Sc > BUDGETF) { nlo = tc; nslo = Sc; }
                    else { nhi = tc; nshi = Sc; crossed = true; }
                }
            }
            lo = nlo; hi = nhi; slo = nslo; shi = nshi;
        }
        float denom = slo - shi;
        tau = (denom > 1e-12f)
            ? lo + (slo - BUDGETF) * (hi - lo) / denom
            : 0.5f * (lo + hi);
    }

    int qe = qe_arr[b];
    int clen = len - 1;
    for (int p = tid; p < LC; p += NT) {
        float r;
        if (p < qe) {
            r = 1.f;
        } else {
            int idx = p - qe + 1;                 // >= 1
            r = (idx <= clen) ? clip01(sp[idx] - tau) : 0.f;
        }
        out[b * LC + p] = r;
    }
}

// ---------------------------------------------------------------------------
extern "C" void kernel_launch(void* const* d_in, const int* in_sizes, int n_in,
                              void* d_out, int out_size) {
    const float* question = (const float*)d_in[0];  // [B,1,H]
    const float* context  = (const float*)d_in[1];  // [B,LC,H]
    const float* Wq       = (const float*)d_in[2];  // [H,P]
    const float* bq       = (const float*)d_in[3];  // [P]
    const float* Wc       = (const float*)d_in[4];  // [H,P]
    const float* bc       = (const float*)d_in[5];  // [P]
    const int*   maskp    = (const int*)d_in[6];    // [B,LC]
    const int*   qep      = (const int*)d_in[7];    // [B]
    float* out = (float*)d_out;                     // [B,MAXLEN]

    dim3 gp(NB, 4);
    proj_kernel<<<gp, 512>>>(question, Wq, bq, Wc, bc, maskp);
    score_tau_kernel<<<ST_BLOCKS, 512>>>(context, qep, out);
}

// round 17
// speedup vs baseline: 1.0600x; 1.0600x over previous
#include <cuda_runtime.h>

#define NB 64
#define LC 4096
#define HD 768
#define PD 128
#define BUDGETF 200.0f

// Scratch (allocation-free rule: __device__ globals)
__device__ float d_U[NB * HD];      // u_b = Wc @ q_b
__device__ float d_qbias[NB];       // q_b . bc
__device__ int   d_len[NB];         // valid context length per batch
__device__ float d_s[NB * LC];      // match scores (only [0,len) valid)

// ---------------------------------------------------------------------------
// Kernel 1 (fused, grid 64x4): every block recomputes q_b (redundant stage A,
// Wq L2-resident so the 4x re-read is free), then computes its 192-row chunk
// of u_b = Wc @ q_b with 16 warps. Chunk-0 blocks also do mask count + qbias.
// (R15 form, measured fast.)
// ---------------------------------------------------------------------------
__global__ void __launch_bounds__(512) proj_kernel(const float* __restrict__ qr,
                                                   const float* __restrict__ Wq,
                                                   const float* __restrict__ bq,
                                                   const float* __restrict__ Wc,
                                                   const float* __restrict__ bc,
                                                   const int* __restrict__ mask) {
    int b = blockIdx.x;
    int chunk = blockIdx.y;           // 0..3, owns h in [chunk*192, chunk*192+192)
    __shared__ float sh_qr[HD];
    __shared__ float sh_part[512];
    __shared__ float sh_q[PD];
    __shared__ int sh_cnt[16];
    int tid = threadIdx.x;
    int warp = tid >> 5, lane = tid & 31;

    for (int i = tid; i < HD; i += 512) sh_qr[i] = qr[b * HD + i];

    // len[b] = sum(mask[b,:])   (chunk 0 only)
    if (chunk == 0) {
        int cnt = 0;
        for (int i = tid; i < LC; i += 512) cnt += mask[b * LC + i];
        #pragma unroll
        for (int off = 16; off; off >>= 1)
            cnt += __shfl_xor_sync(0xffffffffu, cnt, off);
        if (lane == 0) sh_cnt[warp] = cnt;
    }
    __syncthreads();
    if (chunk == 0 && tid == 0) {
        int t = 0;
        #pragma unroll
        for (int w = 0; w < 16; w++) t += sh_cnt[w];
        d_len[b] = t;
    }

    // Stage A (redundant per block): q[p] = qr . Wq[:,p] + bq[p]
    int p = tid & 127;
    int slice = tid >> 7;             // 0..3
    int h0 = slice * (HD / 4);        // 192 rows per slice
    float a0 = 0.f, a1 = 0.f, a2 = 0.f, a3 = 0.f;
    #pragma unroll 4
    for (int h = h0; h < h0 + HD / 4; h += 4) {
        a0 = fmaf(sh_qr[h + 0], Wq[(h + 0) * PD + p], a0);
        a1 = fmaf(sh_qr[h + 1], Wq[(h + 1) * PD + p], a1);
        a2 = fmaf(sh_qr[h + 2], Wq[(h + 2) * PD + p], a2);
        a3 = fmaf(sh_qr[h + 3], Wq[(h + 3) * PD + p], a3);
    }
    sh_part[tid] = (a0 + a1) + (a2 + a3);
    __syncthreads();

    if (tid < PD) {
        sh_q[tid] = sh_part[tid] + sh_part[PD + tid] + sh_part[2 * PD + tid]
                  + sh_part[3 * PD + tid] + bq[tid];
    }
    __syncthreads();

    // qbias = q . bc   (chunk 0 only)
    if (chunk == 0 && tid < 32) {
        float v = 0.f;
        #pragma unroll
        for (int k = 0; k < 4; k++)
            v = fmaf(sh_q[tid + 32 * k], bc[tid + 32 * k], v);
        #pragma unroll
        for (int off = 16; off; off >>= 1)
            v += __shfl_xor_sync(0xffffffffu, v, off);
        if (tid == 0) d_qbias[b] = v;
    }

    // Stage B: u[h] = Wc[h,:] . q for this chunk's 192 rows (16 warps)
    for (int hh = warp; hh < HD / 4; hh += 16) {
        int h = chunk * (HD / 4) + hh;
        const float* wr = Wc + (size_t)h * PD;
        float acc = wr[lane] * sh_q[lane];
        acc = fmaf(wr[lane + 32], sh_q[lane + 32], acc);
        acc = fmaf(wr[lane + 64], sh_q[lane + 64], acc);
        acc = fmaf(wr[lane + 96], sh_q[lane + 96], acc);
        #pragma unroll
        for (int off = 16; off; off >>= 1)
            acc += __shfl_xor_sync(0xffffffffu, acc, off);
        if (lane == 0) d_U[b * HD + h] = acc;
    }
}

// ---------------------------------------------------------------------------
// Kernel 2: s[b,j] = ctx[b,j,:].u_b + qbias for j < len[b].
// Row-interleaved single-row loop, 256 thr x 1184 blocks — the measured
// pattern-ceiling shape (~6.1 TB/s). Every deviation (2-row pairing,
// work-stealing, 512-thr fusion, register hoisting) regressed.
// ---------------------------------------------------------------------------
#define SCORE_BLOCKS 1184
#define NWARPS (SCORE_BLOCKS * 8)

__global__ void __launch_bounds__(256) score_kernel(const float* __restrict__ ctx) {
    __shared__ int sh_len[NB];
    __shared__ float sh_qb[NB];
    int tid = threadIdx.x;
    if (tid < NB) { sh_len[tid] = d_len[tid]; sh_qb[tid] = d_qbias[tid]; }
    __syncthreads();

    int warp = tid >> 5, lane = tid & 31;
    int gw = blockIdx.x * 8 + warp;

    for (int r = gw; r < NB * LC; r += NWARPS) {
        int b = r >> 12;                 // LC = 4096
        int j = r & (LC - 1);
        if (j >= sh_len[b]) continue;    // uniform within warp

        const float4* row = (const float4*)(ctx + (size_t)r * HD);
        const float4* u4  = (const float4*)(d_U + b * HD);
        float acc = 0.f;
        #pragma unroll
        for (int i = 0; i < 6; i++) {    // 192 float4 / 32 lanes
            float4 v = __ldcs(row + lane + 32 * i);
            float4 w = __ldg(u4 + lane + 32 * i);
            acc = fmaf(v.x, w.x, acc);
            acc = fmaf(v.y, w.y, acc);
            acc = fmaf(v.z, w.z, acc);
            acc = fmaf(v.w, w.w, acc);
        }
        #pragma unroll
        for (int off = 16; off; off >>= 1)
            acc += __shfl_xor_sync(0xffffffffu, acc, off);
        if (lane == 0) d_s[r] = acc + sh_qb[b];
    }
}

// ---------------------------------------------------------------------------
// Kernel 3: tau solve — 6 rounds of 8-ary search with tracked endpoint sums,
// final secant step (S piecewise-linear; bracket 1.9e-4 holds <=1 breakpoint
// so the secant is near-exact). 2 barriers/round via double-buffered
// partials. Fused scatter tail. (R12 form, measured 10.8us.)
// ---------------------------------------------------------------------------
__device__ __forceinline__ float clip01(float v) {
    return fminf(fmaxf(v, 0.f), 1.f);
}

__global__ void __launch_bounds__(512) tau_kernel(const int* __restrict__ qe_arr,
                                                  float* __restrict__ out) {
    int b = blockIdx.x;
    const int NT = 512;
    __shared__ float redf[2][16 * 7];
    __shared__ float sh_tot[2][8];
    int tid = threadIdx.x, warp = tid >> 5, lane = tid & 31;
    int len = d_len[b];
    const float* sp = d_s + b * LC;

    // register-resident values; invalid -> -1e5 (contributes 0, never max)
    float v[8];
    #pragma unroll
    for (int k = 0; k < 8; k++) {
        int i = tid + k * NT;
        v[k] = (i < len) ? sp[i] : -100000.0f;
    }

    // max and z_sum(0), fused hierarchical block reduce
    float mx = -100000.0f, sum0 = 0.f;
    #pragma unroll
    for (int k = 0; k < 8; k++) {
        mx = fmaxf(mx, v[k]);
        sum0 += clip01(v[k]);
    }
    {
        #pragma unroll
        for (int off = 16; off; off >>= 1) {
            mx   = fmaxf(mx, __shfl_xor_sync(0xffffffffu, mx, off));
            sum0 += __shfl_xor_sync(0xffffffffu, sum0, off);
        }
        if (lane == 0) { redf[0][warp * 2] = mx; redf[0][warp * 2 + 1] = sum0; }
        __syncthreads();
        if (tid == 0) {
            float a = redf[0][0], s = redf[0][1];
            #pragma unroll
            for (int w = 1; w < 16; w++) {
                a = fmaxf(a, redf[0][w * 2]);
                s += redf[0][w * 2 + 1];
            }
            sh_tot[1][0] = a; sh_tot[1][1] = s;   // park in buffer 1 (round 0 uses buffer 0)
        }
        __syncthreads();
        mx = sh_tot[1][0]; sum0 = sh_tot[1][1];
    }

    float tau = 0.f;
    if (sum0 > BUDGETF) {
        float lo = 0.f, hi = mx;
        float slo = sum0, shi = 0.f;      // S at the bracket endpoints
        for (int it = 0; it < 6; it++) {
            int par = it & 1;
            float step = (hi - lo) * 0.125f;
            float part[7];
            #pragma unroll
            for (int c = 0; c < 7; c++) part[c] = 0.f;
            #pragma unroll
            for (int k = 0; k < 8; k++) {
                float x = v[k] - lo;
                #pragma unroll
                for (int c = 0; c < 7; c++)
                    part[c] += clip01(x - (c + 1) * step);
            }
            #pragma unroll
            for (int c = 0; c < 7; c++) {
                #pragma unroll
                for (int off = 16; off; off >>= 1)
                    part[c] += __shfl_xor_sync(0xffffffffu, part[c], off);
            }
            if (lane == 0) {
                #pragma unroll
                for (int c = 0; c < 7; c++) redf[par][warp * 7 + c] = part[c];
            }
            __syncthreads();               // barrier 1: partials ready
            if (tid < 7) {
                float t = redf[par][tid];
                #pragma unroll
                for (int w = 1; w < 16; w++) t += redf[par][w * 7 + tid];
                sh_tot[par][tid] = t;
            }
            __syncthreads();               // barrier 2: totals ready
            // S non-increasing: lo -> last candidate with S>BUDGET,
            // hi -> first with S<=BUDGET. Track endpoint sums for secant.
            float nlo = lo, nhi = hi, nslo = slo, nshi = shi;
            bool crossed = false;
            #pragma unroll
            for (int c = 0; c < 7; c++) {
                float tc = lo + (c + 1) * step;
                float Sc = sh_tot[par][c];
                if (!crossed) {
                    if (Sc > BUDGETF) { nlo = tc; nslo = Sc; }
                    else { nhi = tc; nshi = Sc; crossed = true; }
                }
            }
            lo = nlo; hi = nhi; slo = nslo; shi = nshi;
            // no 3rd barrier: next round writes the OTHER parity buffer; its
            // barrier 1 orders these reads before this buffer is rewritten.
        }
        // final secant step on the (near-)linear segment
        float denom = slo - shi;
        tau = (denom > 1e-12f)
            ? lo + (slo - BUDGETF) * (hi - lo) / denom
            : 0.5f * (lo + hi);
    }

    // fused scatter tail: out[b,p] = 1 | clip01(s[idx]-tau) | 0
    int qe = qe_arr[b];
    int clen = len - 1;
    for (int p = tid; p < LC; p += NT) {
        float r;
        if (p < qe) {
            r = 1.f;
        } else {
            int idx = p - qe + 1;                 // >= 1
            r = (idx <= clen) ? clip01(sp[idx] - tau) : 0.f;
        }
        out[b * LC + p] = r;
    }
}

// ---------------------------------------------------------------------------
extern "C" void kernel_launch(void* const* d_in, const int* in_sizes, int n_in,
                              void* d_out, int out_size) {
    const float* question = (const float*)d_in[0];  // [B,1,H]
    const float* context  = (const float*)d_in[1];  // [B,LC,H]
    const float* Wq       = (const float*)d_in[2];  // [H,P]
    const float* bq       = (const float*)d_in[3];  // [P]
    const float* Wc       = (const float*)d_in[4];  // [H,P]
    const float* bc       = (const float*)d_in[5];  // [P]
    const int*   maskp    = (const int*)d_in[6];    // [B,LC]
    const int*   qep      = (const int*)d_in[7];    // [B]
    float* out = (float*)d_out;                     // [B,MAXLEN]

    dim3 gp(NB, 4);
    proj_kernel<<<gp, 512>>>(question, Wq, bq, Wc, bc, maskp);
    score_kernel<<<SCORE_BLOCKS, 256>>>(context);
    tau_kernel<<<NB, 512>>>(qep, out);
}